// round 1
// baseline (speedup 1.0000x reference)
#include <cuda_runtime.h>
#include <cuda_bf16.h>
#include <cstdint>

// Problem constants
#define BATCH   8
#define NELEM   262144          // 2^18
#define NSHIFT  18
#define TOPK    6000
#define NOUT    1000
#define NMS_THR 0.7f
#define BINS    (1 << 18)       // 18-bit prefix of float bits (bits >> 14)
#define BIN_SHIFT 14
#define SORTN   8192            // power of two >= TOPK (+ boundary slack)
#define NMS_THREADS 1024
#define SLOTS_PER_THREAD 6      // ceil(6000/1024)

typedef unsigned long long u64;
typedef unsigned int u32;

// ---------------- static device scratch (no allocations allowed) ----------------
__device__ u32 g_hist[BATCH * BINS];          // 8 MB
__device__ u64 g_main[BATCH * TOPK];          // strictly-above-threshold keys
__device__ u64 g_bnd[BATCH * NELEM];          // boundary-bin keys (worst case)
__device__ u32 g_cnt_main[BATCH];
__device__ u32 g_cnt_bnd[BATCH];
__device__ u32 g_pbin[BATCH];
__device__ u32 g_above[BATCH];

// ---------------- kernel 0: zero scratch ----------------
__global__ void k_zero() {
    u32 i = blockIdx.x * blockDim.x + threadIdx.x;
    if (i < BATCH * BINS) g_hist[i] = 0;
    if (i < BATCH) { g_cnt_main[i] = 0; g_cnt_bnd[i] = 0; }
}

// ---------------- kernel 1: histogram of score-bit prefixes ----------------
__global__ void k_hist(const float2* __restrict__ cls) {
    u32 i = blockIdx.x * blockDim.x + threadIdx.x;   // i in [0, BATCH*NELEM)
    float s = cls[i].y;                              // rpn_class[..., 1]
    u32 bits = __float_as_uint(s);
    u32 bin = bits >> BIN_SHIFT;                     // 18 bits (scores positive)
    u32 b = i >> NSHIFT;
    atomicAdd(&g_hist[(b << 18) + bin], 1u);
}

// ---------------- kernel 2: find per-batch threshold bin ----------------
__global__ void __launch_bounds__(1024) k_select() {
    int b = blockIdx.x;
    int tid = threadIdx.x;
    const int CH = BINS / 1024;                      // 256 bins per thread
    const u32* hist = &g_hist[b * BINS];

    u32 mysum = 0;
    int base = tid * CH;
    #pragma unroll 8
    for (int k = 0; k < CH; k++) mysum += hist[base + k];

    __shared__ u32 ss[1024];
    ss[tid] = mysum;
    __syncthreads();
    // inclusive suffix sum: ss[c] = sum over chunks >= c
    for (int off = 1; off < 1024; off <<= 1) {
        u32 v = (tid + off < 1024) ? ss[tid + off] : 0u;
        __syncthreads();
        ss[tid] += v;
        __syncthreads();
    }
    u32 A = ss[tid] - mysum;                         // strictly-above count (higher chunks)
    if (A < TOPK && A + mysum >= TOPK) {
        // boundary bin is inside this chunk; scan from highest bin down
        u32 acc = A;
        for (int bin = base + CH - 1; bin >= base; --bin) {
            u32 h = hist[bin];
            if (acc + h >= TOPK) { g_pbin[b] = (u32)bin; g_above[b] = acc; break; }
            acc += h;
        }
    }
}

// ---------------- kernel 3: compaction ----------------
__global__ void k_compact(const float2* __restrict__ cls) {
    u32 i = blockIdx.x * blockDim.x + threadIdx.x;
    float s = cls[i].y;
    u32 bits = __float_as_uint(s);
    u32 bin = bits >> BIN_SHIFT;
    u32 b = i >> NSHIFT;
    u32 idx = i & (NELEM - 1);
    u32 p = g_pbin[b];
    if (bin > p) {
        u32 pos = atomicAdd(&g_cnt_main[b], 1u);
        g_main[b * TOPK + pos] = ((u64)bits << 32) | (u32)(~idx);
    } else if (bin == p) {
        u32 pos = atomicAdd(&g_cnt_bnd[b], 1u);
        g_bnd[(u32)b * NELEM + pos] = ((u64)bits << 32) | (u32)(~idx);
    }
}

// ---------------- kernel 4: sort + decode boxes + sequential NMS ----------------
__device__ __forceinline__ float iou_ref(float4 a, float4 c) {
    float y1 = fmaxf(a.x, c.x);
    float x1 = fmaxf(a.y, c.y);
    float y2 = fminf(a.z, c.z);
    float x2 = fminf(a.w, c.w);
    float inter = fmaxf(y2 - y1, 0.0f) * fmaxf(x2 - x1, 0.0f);
    float areaA = (a.z - a.x) * (a.w - a.y);
    float areaC = (c.z - c.x) * (c.w - c.y);
    return inter / (areaA + areaC - inter + 1e-9f);
}

__global__ void __launch_bounds__(NMS_THREADS, 1)
k_nms(const float4* __restrict__ bbox, const float4* __restrict__ anchors,
      float4* __restrict__ out) {
    extern __shared__ __align__(16) unsigned char smem_raw[];
    u64*    keys  = (u64*)smem_raw;                        // 8192 * 8  = 65536
    float4* boxes = (float4*)(smem_raw + 65536);           // 6000 * 16 = 96000
    char*   flags = (char*)(smem_raw + 65536 + 96000);     // 6016

    int b = blockIdx.x;
    int tid = threadIdx.x;
    int lane = tid & 31;
    int wid = tid >> 5;

    u32 cnt_main = g_cnt_main[b];
    u32 m = g_cnt_bnd[b];
    u32 total = cnt_main + m;

    // load main keys
    for (u32 i = tid; i < cnt_main; i += NMS_THREADS) keys[i] = g_main[b * TOPK + i];

    if (total <= SORTN) {
        for (u32 i = tid; i < m; i += NMS_THREADS) keys[cnt_main + i] = g_bnd[(u32)b * NELEM + i];
        for (u32 i = total + tid; i < SORTN; i += NMS_THREADS) keys[i] = 0ull;
        __syncthreads();
    } else {
        // pathological fallback: iteratively select top-r boundary keys
        for (u32 i = cnt_main + tid; i < SORTN; i += NMS_THREADS) keys[i] = 0ull;
        __syncthreads();
        static __shared__ u64 rk[32];
        static __shared__ u32 rp[32];
        int r = TOPK - (int)cnt_main;
        for (int round = 0; round < r; ++round) {
            u64 bk = 0; u32 bp = 0;
            for (u32 i = tid; i < m; i += NMS_THREADS) {
                u64 v = g_bnd[(u32)b * NELEM + i];
                if (v > bk) { bk = v; bp = i; }
            }
            for (int off = 16; off; off >>= 1) {
                u64 ok = __shfl_down_sync(0xFFFFFFFFu, bk, off);
                u32 op = __shfl_down_sync(0xFFFFFFFFu, bp, off);
                if (ok > bk) { bk = ok; bp = op; }
            }
            if (lane == 0) { rk[wid] = bk; rp[wid] = bp; }
            __syncthreads();
            if (wid == 0) {
                bk = rk[lane]; bp = rp[lane];
                for (int off = 16; off; off >>= 1) {
                    u64 ok = __shfl_down_sync(0xFFFFFFFFu, bk, off);
                    u32 op = __shfl_down_sync(0xFFFFFFFFu, bp, off);
                    if (ok > bk) { bk = ok; bp = op; }
                }
                if (lane == 0) {
                    keys[cnt_main + round] = bk;
                    g_bnd[(u32)b * NELEM + bp] = 0ull;
                }
            }
            __syncthreads();
        }
    }

    // bitonic sort descending, SORTN u64 keys
    for (u32 k = 2; k <= SORTN; k <<= 1) {
        for (u32 j = k >> 1; j; j >>= 1) {
            for (u32 i = tid; i < SORTN; i += NMS_THREADS) {
                u32 ix = i ^ j;
                if (ix > i) {
                    u64 a = keys[i], c = keys[ix];
                    bool dirDesc = ((i & k) == 0);
                    if ((a < c) == dirDesc) { keys[i] = c; keys[ix] = a; }
                }
            }
            __syncthreads();
        }
    }

    // decode boxes for top TOPK slots; cache own slots in registers
    float4 mb[SLOTS_PER_THREAD];
    bool alive[SLOTS_PER_THREAD];
    #pragma unroll
    for (int j = 0; j < SLOTS_PER_THREAD; j++) {
        int s = tid + j * NMS_THREADS;
        alive[j] = (s < TOPK);
        if (s < TOPK) {
            u64 key = keys[s];
            u32 idx = ~(u32)(key & 0xFFFFFFFFull);
            u32 gi = ((u32)b << NSHIFT) + idx;
            float4 a = anchors[gi];
            float4 d = bbox[gi];
            d.x *= 0.1f; d.y *= 0.1f; d.z *= 0.2f; d.w *= 0.2f;
            float h = a.z - a.x;
            float w = a.w - a.y;
            float cy = a.x + 0.5f * h;
            float cx = a.y + 0.5f * w;
            cy = cy + d.x * h;
            cx = cx + d.y * w;
            h = h * expf(d.z);
            w = w * expf(d.w);
            float4 box;
            box.x = fminf(fmaxf(cy - 0.5f * h, 0.0f), 1.0f);
            box.y = fminf(fmaxf(cx - 0.5f * w, 0.0f), 1.0f);
            box.z = fminf(fmaxf(cy + 0.5f * h, 0.0f), 1.0f);
            box.w = fminf(fmaxf(cx + 0.5f * w, 0.0f), 1.0f);
            boxes[s] = box;
            flags[s] = 0;
            mb[j] = box;
        }
    }
    __syncthreads();

    // sequential greedy NMS over sorted candidates
    float4* outb = out + b * NOUT;
    int ptr = 0;   // identical in all threads
    int t;
    for (t = 0; t < NOUT; t++) {
        while (ptr < TOPK && flags[ptr]) ++ptr;      // broadcast SMEM reads
        if (ptr >= TOPK) break;
        int w = ptr;
        float4 wb = boxes[w];
        __syncthreads();                             // scans done before flag writes
        #pragma unroll
        for (int j = 0; j < SLOTS_PER_THREAD; j++) {
            int s = tid + j * NMS_THREADS;
            if (alive[j]) {
                if (s == w) {
                    alive[j] = false; flags[s] = 1;
                } else {
                    float iou = iou_ref(wb, mb[j]);
                    if (iou > NMS_THR) { alive[j] = false; flags[s] = 1; }
                }
            }
        }
        if (tid == 0) outb[t] = wb;
        ++ptr;
        __syncthreads();                             // flags visible for next scan
    }
    // zero-fill remaining proposals (reference outputs zeros when exhausted)
    for (int q = t + tid; q < NOUT; q += NMS_THREADS) {
        outb[q] = make_float4(0.0f, 0.0f, 0.0f, 0.0f);
    }
}

// ---------------- launch ----------------
extern "C" void kernel_launch(void* const* d_in, const int* in_sizes, int n_in,
                              void* d_out, int out_size) {
    const float2* cls     = (const float2*)d_in[0];   // rpn_class (B,N,2)
    const float4* bbox    = (const float4*)d_in[1];   // rpn_bbox  (B,N,4)
    const float4* anchors = (const float4*)d_in[2];   // anchors   (B,N,4)
    float4* out = (float4*)d_out;                     // (B,1000,4)

    (void)in_sizes; (void)n_in; (void)out_size;

    const int total = BATCH * NELEM;

    k_zero<<<(BATCH * BINS + 1023) / 1024, 1024>>>();
    k_hist<<<total / 1024, 1024>>>(cls);
    k_select<<<BATCH, 1024>>>();
    k_compact<<<total / 1024, 1024>>>(cls);

    static const size_t smem_bytes = 65536 + 96000 + 6016;
    cudaFuncSetAttribute(k_nms, cudaFuncAttributeMaxDynamicSharedMemorySize,
                         (int)smem_bytes);
    k_nms<<<BATCH, NMS_THREADS, smem_bytes>>>(bbox, anchors, out);
}

// round 3
// speedup vs baseline: 2.1484x; 2.1484x over previous
#include <cuda_runtime.h>
#include <cuda_bf16.h>
#include <cstdint>

// Problem constants
#define BATCH   8
#define NELEM   262144          // 2^18
#define NSHIFT  18
#define TOPK    6000
#define NOUT    1000
#define NMS_THR 0.7f
#define BINS    (1 << 18)
#define BIN_SHIFT 14
#define SORTN   8192
#define NPAD    6016            // 94 * 64
#define NWORDS  94

typedef unsigned long long u64;
typedef unsigned int u32;

// ---------------- static device scratch ----------------
__device__ u32 g_hist[BATCH * BINS];            // 8 MB
__device__ u64 g_main[BATCH * TOPK];
__device__ u64 g_bnd[BATCH * NELEM];
__device__ u32 g_cnt_main[BATCH];
__device__ u32 g_cnt_bnd[BATCH];
__device__ u32 g_pbin[BATCH];

__device__ float4 g_sbox[BATCH][NPAD];          // sorted, decoded, clipped boxes
__device__ float  g_area[BATCH][NPAD];          // areas of sorted boxes
__device__ u64    g_mask[BATCH][NPAD][NWORDS];  // 36.2 MB suppression bitmasks

// ---------------- kernel 0: zero scratch ----------------
__global__ void k_zero() {
    u32 i = blockIdx.x * blockDim.x + threadIdx.x;
    if (i < BATCH * BINS) g_hist[i] = 0;
    if (i < BATCH) { g_cnt_main[i] = 0; g_cnt_bnd[i] = 0; }
}

// ---------------- kernel 1: histogram of score-bit prefixes ----------------
__global__ void k_hist(const float2* __restrict__ cls) {
    u32 i = blockIdx.x * blockDim.x + threadIdx.x;
    float s = cls[i].y;
    u32 bits = __float_as_uint(s);
    u32 bin = bits >> BIN_SHIFT;
    u32 b = i >> NSHIFT;
    atomicAdd(&g_hist[(b << 18) + bin], 1u);
}

// ---------------- kernel 2: find per-batch threshold bin ----------------
__global__ void __launch_bounds__(1024) k_select() {
    int b = blockIdx.x;
    int tid = threadIdx.x;
    const int CH = BINS / 1024;
    const u32* hist = &g_hist[b * BINS];

    u32 mysum = 0;
    int base = tid * CH;
    #pragma unroll 8
    for (int k = 0; k < CH; k++) mysum += hist[base + k];

    __shared__ u32 ss[1024];
    ss[tid] = mysum;
    __syncthreads();
    for (int off = 1; off < 1024; off <<= 1) {
        u32 v = (tid + off < 1024) ? ss[tid + off] : 0u;
        __syncthreads();
        ss[tid] += v;
        __syncthreads();
    }
    u32 A = ss[tid] - mysum;                     // strictly-above count
    if (A < TOPK && A + mysum >= TOPK) {
        u32 acc = A;
        for (int bin = base + CH - 1; bin >= base; --bin) {
            u32 h = hist[bin];
            if (acc + h >= TOPK) { g_pbin[b] = (u32)bin; break; }
            acc += h;
        }
    }
}

// ---------------- kernel 3: compaction ----------------
__global__ void k_compact(const float2* __restrict__ cls) {
    u32 i = blockIdx.x * blockDim.x + threadIdx.x;
    float s = cls[i].y;
    u32 bits = __float_as_uint(s);
    u32 bin = bits >> BIN_SHIFT;
    u32 b = i >> NSHIFT;
    u32 idx = i & (NELEM - 1);
    u32 p = g_pbin[b];
    if (bin > p) {
        u32 pos = atomicAdd(&g_cnt_main[b], 1u);
        g_main[b * TOPK + pos] = ((u64)bits << 32) | (u32)(~idx);
    } else if (bin == p) {
        u32 pos = atomicAdd(&g_cnt_bnd[b], 1u);
        g_bnd[(u32)b * NELEM + pos] = ((u64)bits << 32) | (u32)(~idx);
    }
}

// ---------------- kernel 4: sort keys, decode boxes -> global ----------------
__global__ void __launch_bounds__(1024, 1)
k_sort(const float4* __restrict__ bbox, const float4* __restrict__ anchors) {
    extern __shared__ __align__(16) unsigned char smem_raw[];
    u64* keys = (u64*)smem_raw;                 // 8192 * 8 = 65536

    int b = blockIdx.x;
    int tid = threadIdx.x;
    int lane = tid & 31;
    int wid = tid >> 5;

    u32 cnt_main = g_cnt_main[b];
    u32 m = g_cnt_bnd[b];
    u32 total = cnt_main + m;

    for (u32 i = tid; i < cnt_main; i += 1024) keys[i] = g_main[b * TOPK + i];

    if (total <= SORTN) {
        for (u32 i = tid; i < m; i += 1024) keys[cnt_main + i] = g_bnd[(u32)b * NELEM + i];
        for (u32 i = total + tid; i < SORTN; i += 1024) keys[i] = 0ull;
        __syncthreads();
    } else {
        // pathological fallback: iteratively select top-r boundary keys
        for (u32 i = cnt_main + tid; i < SORTN; i += 1024) keys[i] = 0ull;
        __syncthreads();
        __shared__ u64 rk[32];
        __shared__ u32 rp[32];
        int r = TOPK - (int)cnt_main;
        for (int round = 0; round < r; ++round) {
            u64 bk = 0; u32 bp = 0;
            for (u32 i = tid; i < m; i += 1024) {
                u64 v = g_bnd[(u32)b * NELEM + i];
                if (v > bk) { bk = v; bp = i; }
            }
            for (int off = 16; off; off >>= 1) {
                u64 ok = __shfl_down_sync(0xFFFFFFFFu, bk, off);
                u32 op = __shfl_down_sync(0xFFFFFFFFu, bp, off);
                if (ok > bk) { bk = ok; bp = op; }
            }
            if (lane == 0) { rk[wid] = bk; rp[wid] = bp; }
            __syncthreads();
            if (wid == 0) {
                bk = rk[lane]; bp = rp[lane];
                for (int off = 16; off; off >>= 1) {
                    u64 ok = __shfl_down_sync(0xFFFFFFFFu, bk, off);
                    u32 op = __shfl_down_sync(0xFFFFFFFFu, bp, off);
                    if (ok > bk) { bk = ok; bp = op; }
                }
                if (lane == 0) {
                    keys[cnt_main + round] = bk;
                    g_bnd[(u32)b * NELEM + bp] = 0ull;
                }
            }
            __syncthreads();
        }
    }

    // bitonic sort descending
    for (u32 k = 2; k <= SORTN; k <<= 1) {
        for (u32 j = k >> 1; j; j >>= 1) {
            for (u32 i = tid; i < SORTN; i += 1024) {
                u32 ix = i ^ j;
                if (ix > i) {
                    u64 a = keys[i], c = keys[ix];
                    bool dirDesc = ((i & k) == 0);
                    if ((a < c) == dirDesc) { keys[i] = c; keys[ix] = a; }
                }
            }
            __syncthreads();
        }
    }

    // decode boxes for top slots, write to global (+ zero pad)
    for (int s = tid; s < NPAD; s += 1024) {
        if (s < TOPK) {
            u64 key = keys[s];
            u32 idx = ~(u32)(key & 0xFFFFFFFFull);
            u32 gi = ((u32)b << NSHIFT) + idx;
            float4 a = anchors[gi];
            float4 d = bbox[gi];
            d.x *= 0.1f; d.y *= 0.1f; d.z *= 0.2f; d.w *= 0.2f;
            float h = a.z - a.x;
            float w = a.w - a.y;
            float cy = a.x + 0.5f * h;
            float cx = a.y + 0.5f * w;
            cy = cy + d.x * h;
            cx = cx + d.y * w;
            h = h * expf(d.z);
            w = w * expf(d.w);
            float4 box;
            box.x = fminf(fmaxf(cy - 0.5f * h, 0.0f), 1.0f);
            box.y = fminf(fmaxf(cx - 0.5f * w, 0.0f), 1.0f);
            box.z = fminf(fmaxf(cy + 0.5f * h, 0.0f), 1.0f);
            box.w = fminf(fmaxf(cx + 0.5f * w, 0.0f), 1.0f);
            g_sbox[b][s] = box;
            g_area[b][s] = (box.z - box.x) * (box.w - box.y);
        } else {
            g_sbox[b][s] = make_float4(0.0f, 0.0f, 0.0f, 0.0f);
            g_area[b][s] = 0.0f;
        }
    }
}

// ---------------- kernel 5: pairwise IoU suppression bitmask ----------------
__global__ void __launch_bounds__(64) k_mask() {
    int cc = blockIdx.x;        // column chunk
    int rc = blockIdx.y;        // row chunk
    int b  = blockIdx.z;
    if (cc < rc) return;        // only j > i contributes

    __shared__ float4 cbox[64];
    __shared__ float  carea[64];
    int t = threadIdx.x;
    int col0 = cc << 6;
    cbox[t]  = g_sbox[b][col0 + t];
    carea[t] = g_area[b][col0 + t];
    __syncthreads();

    int i = (rc << 6) + t;
    float4 a = g_sbox[b][i];
    float areaA = g_area[b][i];

    u64 bits = 0;
    #pragma unroll 8
    for (int j = 0; j < 64; j++) {
        int cj = col0 + j;
        if (cj > i) {
            float4 c = cbox[j];
            float y1 = fmaxf(a.x, c.x);
            float x1 = fmaxf(a.y, c.y);
            float y2 = fminf(a.z, c.z);
            float x2 = fminf(a.w, c.w);
            float inter = fmaxf(y2 - y1, 0.0f) * fmaxf(x2 - x1, 0.0f);
            float iou = inter / (areaA + carea[j] - inter + 1e-9f);
            if (iou > NMS_THR) bits |= (1ull << j);
        }
    }
    g_mask[b][i][cc] = bits;
}

// ---------------- kernel 6: serial greedy pass over bitmasks ----------------
__global__ void __launch_bounds__(32) k_seq(float4* __restrict__ out) {
    int b = blockIdx.x;
    int lane = threadIdx.x;

    __shared__ u64 remv[NWORDS];
    for (int r = lane; r < NWORDS; r += 32) remv[r] = 0ull;
    __syncwarp();

    const float4* sb = g_sbox[b];
    float4* ob = out + b * NOUT;
    int cnt = 0;

    for (int w = 0; w < NWORDS && cnt < NOUT; w++) {
        u64 live = (w == NWORDS - 1) ? ((1ull << 48) - 1ull) : ~0ull;  // 6000 = 93*64 + 48
        while (cnt < NOUT) {
            u64 avail = (~remv[w]) & live;                // broadcast SMEM read
            if (!avail) break;
            int bit = __ffsll((long long)avail) - 1;
            int i = (w << 6) + bit;

            if (lane == 0) ob[cnt] = sb[i];
            cnt++;

            // prefetch the next few mask rows (752B = 6 lines each)
            if (lane < 24) {
                const char* p = (const char*)&g_mask[b][i + 1 + (lane / 6)][0]
                                + (lane % 6) * 128;
                asm volatile("prefetch.global.L1 [%0];" :: "l"(p));
            }

            // suppress: OR mask row (words >= w) into remv; include self bit
            #pragma unroll
            for (int r = 0; r < 3; r++) {
                int j = lane + (r << 5);
                if (j < NWORDS && j >= w) {
                    u64 mrow = g_mask[b][i][j];
                    if (j == w) mrow |= (1ull << bit);
                    remv[j] |= mrow;
                }
            }
            __syncwarp();
        }
    }

    for (int q = cnt + lane; q < NOUT; q += 32)
        ob[q] = make_float4(0.0f, 0.0f, 0.0f, 0.0f);
}

// ---------------- launch ----------------
extern "C" void kernel_launch(void* const* d_in, const int* in_sizes, int n_in,
                              void* d_out, int out_size) {
    const float2* cls     = (const float2*)d_in[0];
    const float4* bbox    = (const float4*)d_in[1];
    const float4* anchors = (const float4*)d_in[2];
    float4* out = (float4*)d_out;

    (void)in_sizes; (void)n_in; (void)out_size;

    const int total = BATCH * NELEM;

    k_zero<<<(BATCH * BINS + 1023) / 1024, 1024>>>();
    k_hist<<<total / 1024, 1024>>>(cls);
    k_select<<<BATCH, 1024>>>();
    k_compact<<<total / 1024, 1024>>>(cls);

    cudaFuncSetAttribute(k_sort, cudaFuncAttributeMaxDynamicSharedMemorySize, 65536);
    k_sort<<<BATCH, 1024, 65536>>>(bbox, anchors);

    dim3 mgrid(NWORDS, NWORDS, BATCH);
    k_mask<<<mgrid, 64>>>();

    k_seq<<<BATCH, 32>>>(out);
}

// round 4
// speedup vs baseline: 2.5002x; 1.1637x over previous
#include <cuda_runtime.h>
#include <cuda_bf16.h>
#include <cstdint>

// Problem constants
#define BATCH   8
#define NELEM   262144          // 2^18
#define NSHIFT  18
#define TOPK    6000
#define NOUT    1000
#define NMS_THR 0.7f
#define BINS    65536           // scores < 1.0 => (bits>>14) <= 65024
#define BIN_SHIFT 14
#define SORTN   8192
#define NPAD    6016            // 94 * 64
#define NPAD2   (NPAD + 20)     // prefetch overrun padding
#define NWORDS  94

typedef unsigned long long u64;
typedef unsigned int u32;

// ---------------- static device scratch ----------------
__device__ u32 g_hist[BATCH * BINS];             // 2 MB
__device__ u64 g_main[BATCH * TOPK];
__device__ u64 g_bnd[BATCH * NELEM];
__device__ u32 g_cnt_main[BATCH];
__device__ u32 g_cnt_bnd[BATCH];
__device__ u32 g_pbin[BATCH];

__device__ float4 g_sbox[BATCH][NPAD];           // sorted, decoded, clipped boxes
__device__ float  g_area[BATCH][NPAD];
__device__ u64    g_mask[BATCH][NPAD2][NWORDS];  // suppression bitmasks (zero-init lower tri)

// ---------------- kernel 0: zero scratch (vectorized) ----------------
__global__ void k_zero(){
    u32 i = blockIdx.x * blockDim.x + threadIdx.x;        // over uint4 groups
    ((uint4*)g_hist)[i] = make_uint4(0u, 0u, 0u, 0u);
    if (i < BATCH) { g_cnt_main[i] = 0; g_cnt_bnd[i] = 0; }
}

// ---------------- kernel 1: histogram of score-bit prefixes ----------------
__global__ void k_hist(const float2* __restrict__ cls) {
    u32 i = blockIdx.x * blockDim.x + threadIdx.x;
    float s = cls[i].y;
    u32 bin = min(__float_as_uint(s) >> BIN_SHIFT, (u32)(BINS - 1));
    u32 b = i >> NSHIFT;
    atomicAdd(&g_hist[b * BINS + bin], 1u);
}

// ---------------- kernel 2: find per-batch threshold bin ----------------
__global__ void __launch_bounds__(1024) k_select() {
    int b = blockIdx.x;
    int tid = threadIdx.x;
    const int CH = BINS / 1024;                  // 64 bins per thread
    const u32* hist = &g_hist[b * BINS];

    u32 mysum = 0;
    int base = tid * CH;
    #pragma unroll 8
    for (int k = 0; k < CH; k++) mysum += hist[base + k];

    __shared__ u32 ss[1024];
    ss[tid] = mysum;
    __syncthreads();
    for (int off = 1; off < 1024; off <<= 1) {
        u32 v = (tid + off < 1024) ? ss[tid + off] : 0u;
        __syncthreads();
        ss[tid] += v;
        __syncthreads();
    }
    u32 A = ss[tid] - mysum;                     // strictly-above count
    if (A < TOPK && A + mysum >= TOPK) {
        u32 acc = A;
        for (int bin = base + CH - 1; bin >= base; --bin) {
            u32 h = hist[bin];
            if (acc + h >= TOPK) { g_pbin[b] = (u32)bin; break; }
            acc += h;
        }
    }
}

// ---------------- kernel 3: compaction ----------------
__global__ void k_compact(const float2* __restrict__ cls) {
    u32 i = blockIdx.x * blockDim.x + threadIdx.x;
    float s = cls[i].y;
    u32 bits = __float_as_uint(s);
    u32 bin = min(bits >> BIN_SHIFT, (u32)(BINS - 1));
    u32 b = i >> NSHIFT;
    u32 idx = i & (NELEM - 1);
    u32 p = g_pbin[b];
    if (bin > p) {
        u32 pos = atomicAdd(&g_cnt_main[b], 1u);
        g_main[b * TOPK + pos] = ((u64)bits << 32) | (u32)(~idx);
    } else if (bin == p) {
        u32 pos = atomicAdd(&g_cnt_bnd[b], 1u);
        g_bnd[(u32)b * NELEM + pos] = ((u64)bits << 32) | (u32)(~idx);
    }
}

// ---------------- kernel 4: sort keys, decode boxes -> global ----------------
__global__ void __launch_bounds__(1024, 1)
k_sort(const float4* __restrict__ bbox, const float4* __restrict__ anchors) {
    extern __shared__ __align__(16) unsigned char smem_raw[];
    u64* keys = (u64*)smem_raw;                  // 8192 * 8 = 65536

    int b = blockIdx.x;
    int tid = threadIdx.x;
    int lane = tid & 31;
    int wid = tid >> 5;

    u32 cnt_main = g_cnt_main[b];
    u32 m = g_cnt_bnd[b];
    u32 total = cnt_main + m;

    for (u32 i = tid; i < cnt_main; i += 1024) keys[i] = g_main[b * TOPK + i];

    if (total <= SORTN) {
        for (u32 i = tid; i < m; i += 1024) keys[cnt_main + i] = g_bnd[(u32)b * NELEM + i];
        for (u32 i = total + tid; i < SORTN; i += 1024) keys[i] = 0ull;
        __syncthreads();
    } else {
        // pathological fallback: iteratively select top-r boundary keys
        for (u32 i = cnt_main + tid; i < SORTN; i += 1024) keys[i] = 0ull;
        __syncthreads();
        __shared__ u64 rk[32];
        __shared__ u32 rp[32];
        int r = TOPK - (int)cnt_main;
        for (int round = 0; round < r; ++round) {
            u64 bk = 0; u32 bp = 0;
            for (u32 i = tid; i < m; i += 1024) {
                u64 v = g_bnd[(u32)b * NELEM + i];
                if (v > bk) { bk = v; bp = i; }
            }
            for (int off = 16; off; off >>= 1) {
                u64 ok = __shfl_down_sync(0xFFFFFFFFu, bk, off);
                u32 op = __shfl_down_sync(0xFFFFFFFFu, bp, off);
                if (ok > bk) { bk = ok; bp = op; }
            }
            if (lane == 0) { rk[wid] = bk; rp[wid] = bp; }
            __syncthreads();
            if (wid == 0) {
                bk = rk[lane]; bp = rp[lane];
                for (int off = 16; off; off >>= 1) {
                    u64 ok = __shfl_down_sync(0xFFFFFFFFu, bk, off);
                    u32 op = __shfl_down_sync(0xFFFFFFFFu, bp, off);
                    if (ok > bk) { bk = ok; bp = op; }
                }
                if (lane == 0) {
                    keys[cnt_main + round] = bk;
                    g_bnd[(u32)b * NELEM + bp] = 0ull;
                }
            }
            __syncthreads();
        }
    }

    // bitonic sort descending
    for (u32 k = 2; k <= SORTN; k <<= 1) {
        for (u32 j = k >> 1; j; j >>= 1) {
            for (u32 i = tid; i < SORTN; i += 1024) {
                u32 ix = i ^ j;
                if (ix > i) {
                    u64 a = keys[i], c = keys[ix];
                    bool dirDesc = ((i & k) == 0);
                    if ((a < c) == dirDesc) { keys[i] = c; keys[ix] = a; }
                }
            }
            __syncthreads();
        }
    }

    // decode boxes for top slots, write to global (+ zero pad)
    for (int s = tid; s < NPAD; s += 1024) {
        if (s < TOPK) {
            u64 key = keys[s];
            u32 idx = ~(u32)(key & 0xFFFFFFFFull);
            u32 gi = ((u32)b << NSHIFT) + idx;
            float4 a = anchors[gi];
            float4 d = bbox[gi];
            d.x *= 0.1f; d.y *= 0.1f; d.z *= 0.2f; d.w *= 0.2f;
            float h = a.z - a.x;
            float w = a.w - a.y;
            float cy = a.x + 0.5f * h;
            float cx = a.y + 0.5f * w;
            cy = cy + d.x * h;
            cx = cx + d.y * w;
            h = h * expf(d.z);
            w = w * expf(d.w);
            float4 box;
            box.x = fminf(fmaxf(cy - 0.5f * h, 0.0f), 1.0f);
            box.y = fminf(fmaxf(cx - 0.5f * w, 0.0f), 1.0f);
            box.z = fminf(fmaxf(cy + 0.5f * h, 0.0f), 1.0f);
            box.w = fminf(fmaxf(cx + 0.5f * w, 0.0f), 1.0f);
            g_sbox[b][s] = box;
            g_area[b][s] = (box.z - box.x) * (box.w - box.y);
        } else {
            g_sbox[b][s] = make_float4(0.0f, 0.0f, 0.0f, 0.0f);
            g_area[b][s] = 0.0f;
        }
    }
}

// ---------------- kernel 5: pairwise IoU suppression bitmask ----------------
// 256 threads = 4 row-chunks of 64 vs one 64-column chunk (shared tile).
__global__ void __launch_bounds__(256) k_mask() {
    int cc  = blockIdx.x;            // column chunk 0..93
    int rc4 = blockIdx.y;            // row quad    0..23
    int b   = blockIdx.z;
    if (cc < (rc4 << 2)) return;     // entire block strictly lower-triangle

    __shared__ float4 cbox[64];
    __shared__ float  carea[64];
    int t = threadIdx.x;
    int col0 = cc << 6;
    if (t < 64) {
        cbox[t]  = g_sbox[b][col0 + t];
        carea[t] = g_area[b][col0 + t];
    }
    __syncthreads();

    int rc = (rc4 << 2) + (t >> 6);
    if (rc > cc || rc >= NWORDS) return;
    int i = (rc << 6) + (t & 63);
    float4 a = g_sbox[b][i];
    float areaA = g_area[b][i];

    u64 bits = 0;
    #pragma unroll 8
    for (int j = 0; j < 64; j++) {
        int cj = col0 + j;
        if (cj > i) {
            float4 c = cbox[j];
            float y1 = fmaxf(a.x, c.x);
            float x1 = fmaxf(a.y, c.y);
            float y2 = fminf(a.z, c.z);
            float x2 = fminf(a.w, c.w);
            float inter = fmaxf(y2 - y1, 0.0f) * fmaxf(x2 - x1, 0.0f);
            float iou = inter / (areaA + carea[j] - inter + 1e-9f);
            if (iou > NMS_THR) bits |= (1ull << j);
        }
    }
    g_mask[b][i][cc] = bits;
}

// ---------------- kernel 6: serial greedy pass over bitmasks ----------------
__global__ void __launch_bounds__(32) k_seq(float4* __restrict__ out) {
    int b = blockIdx.x;
    int lane = threadIdx.x;

    __shared__ u64 remv[NWORDS];
    for (int r = lane; r < NWORDS; r += 32) remv[r] = 0ull;
    __syncwarp();

    const float4* sb = g_sbox[b];
    float4* ob = out + b * NOUT;
    int cnt = 0;

    // warm the L1 with the first rows
    {
        const char* pb = (const char*)&g_mask[b][0][0];
        asm volatile("prefetch.global.L1 [%0];" :: "l"(pb + (u32)lane * 128));
        asm volatile("prefetch.global.L1 [%0];" :: "l"(pb + (u32)(lane + 32) * 128));
        asm volatile("prefetch.global.L1 [%0];" :: "l"(pb + (u32)(lane + 64) * 128));
    }

    for (int w = 0; w < NWORDS && cnt < NOUT; w++) {
        u64 live = (w == NWORDS - 1) ? ((1ull << 48) - 1ull) : ~0ull;  // 6000 = 93*64 + 48
        while (cnt < NOUT) {
            u64 avail = (~remv[w]) & live;                // broadcast SMEM read
            if (!avail) break;
            int bit = __ffsll((long long)avail) - 1;
            int i = (w << 6) + bit;

            if (lane == 0) ob[cnt] = sb[i];
            cnt++;

            // suppress: OR mask row (words >= w) into remv; include self bit
            #pragma unroll
            for (int r = 0; r < 3; r++) {
                int j = lane + (r << 5);
                if (j < NWORDS && j >= w) {
                    u64 mrow = g_mask[b][i][j];
                    if (j == w) mrow |= (1ull << bit);
                    remv[j] |= mrow;
                }
            }

            // prefetch the next ~16 rows (12KB contiguous) into L1
            {
                const char* pb = (const char*)&g_mask[b][i + 1][0];
                asm volatile("prefetch.global.L1 [%0];" :: "l"(pb + (u32)lane * 128));
                asm volatile("prefetch.global.L1 [%0];" :: "l"(pb + (u32)(lane + 32) * 128));
                asm volatile("prefetch.global.L1 [%0];" :: "l"(pb + (u32)(lane + 64) * 128));
            }
            __syncwarp();
        }
    }

    for (int q = cnt + lane; q < NOUT; q += 32)
        ob[q] = make_float4(0.0f, 0.0f, 0.0f, 0.0f);
}

// ---------------- launch ----------------
extern "C" void kernel_launch(void* const* d_in, const int* in_sizes, int n_in,
                              void* d_out, int out_size) {
    const float2* cls     = (const float2*)d_in[0];
    const float4* bbox    = (const float4*)d_in[1];
    const float4* anchors = (const float4*)d_in[2];
    float4* out = (float4*)d_out;

    (void)in_sizes; (void)n_in; (void)out_size;

    const int total = BATCH * NELEM;

    k_zero<<<(BATCH * BINS / 4) / 256, 256>>>();
    k_hist<<<total / 1024, 1024>>>(cls);
    k_select<<<BATCH, 1024>>>();
    k_compact<<<total / 1024, 1024>>>(cls);

    cudaFuncSetAttribute(k_sort, cudaFuncAttributeMaxDynamicSharedMemorySize, 65536);
    k_sort<<<BATCH, 1024, 65536>>>(bbox, anchors);

    dim3 mgrid(NWORDS, (NWORDS + 3) / 4, BATCH);
    k_mask<<<mgrid, 256>>>();

    k_seq<<<BATCH, 32>>>(out);
}

// round 6
// speedup vs baseline: 3.1993x; 1.2796x over previous
#include <cuda_runtime.h>
#include <cuda_bf16.h>
#include <cstdint>

// Problem constants
#define BATCH   8
#define NELEM   262144          // 2^18
#define NSHIFT  18
#define TOPK    6000
#define NOUT    1000
#define NMS_THR 0.7f
#define BINS    65536           // scores < 1.0 => (bits>>14) <= 65024
#define BIN_SHIFT 14
#define SORTN   8192
#define NPAD    6016            // 94 * 64
#define NPAD2   (NPAD + 20)     // prefetch overrun padding
#define NWORDS  94

typedef unsigned long long u64;
typedef unsigned int u32;

// ---------------- static device scratch ----------------
__device__ u32 g_hist[BATCH * BINS];             // 2 MB
__device__ u64 g_main[BATCH * TOPK];
__device__ u64 g_bnd[BATCH * NELEM];
__device__ u32 g_cnt_main[BATCH];
__device__ u32 g_cnt_bnd[BATCH];
__device__ u32 g_pbin[BATCH];

__device__ float4 g_sbox[BATCH][NPAD];           // sorted, decoded, clipped boxes
__device__ float  g_area[BATCH][NPAD];
__device__ u64    g_mask[BATCH][NPAD2][NWORDS];  // suppression bitmasks

// ---------------- kernel 0: zero scratch (vectorized) ----------------
__global__ void k_zero(){
    u32 i = blockIdx.x * blockDim.x + threadIdx.x;        // over uint4 groups
    ((uint4*)g_hist)[i] = make_uint4(0u, 0u, 0u, 0u);
    if (i < BATCH) { g_cnt_main[i] = 0; g_cnt_bnd[i] = 0; }
}

// ---------------- kernel 1: histogram (4 elems/thread) ----------------
__global__ void k_hist(const float4* __restrict__ cls4) {
    u32 i = blockIdx.x * blockDim.x + threadIdx.x;   // group of 4 elements
    float4 p0 = cls4[2 * i];
    float4 p1 = cls4[2 * i + 1];
    u32 b = (i << 2) >> NSHIFT;                      // all 4 in same batch
    u32* h = &g_hist[b * BINS];
    u32 b0 = min(__float_as_uint(p0.y) >> BIN_SHIFT, (u32)(BINS - 1));
    u32 b1 = min(__float_as_uint(p0.w) >> BIN_SHIFT, (u32)(BINS - 1));
    u32 b2 = min(__float_as_uint(p1.y) >> BIN_SHIFT, (u32)(BINS - 1));
    u32 b3 = min(__float_as_uint(p1.w) >> BIN_SHIFT, (u32)(BINS - 1));
    atomicAdd(&h[b0], 1u);
    atomicAdd(&h[b1], 1u);
    atomicAdd(&h[b2], 1u);
    atomicAdd(&h[b3], 1u);
}

// ---------------- kernel 2: find per-batch threshold bin ----------------
__global__ void __launch_bounds__(1024) k_select() {
    int b = blockIdx.x;
    int tid = threadIdx.x;
    const int CH = BINS / 1024;                  // 64 bins per thread
    const u32* hist = &g_hist[b * BINS];

    u32 mysum = 0;
    int base = tid * CH;
    #pragma unroll 8
    for (int k = 0; k < CH; k++) mysum += hist[base + k];

    __shared__ u32 ss[1024];
    ss[tid] = mysum;
    __syncthreads();
    for (int off = 1; off < 1024; off <<= 1) {
        u32 v = (tid + off < 1024) ? ss[tid + off] : 0u;
        __syncthreads();
        ss[tid] += v;
        __syncthreads();
    }
    u32 A = ss[tid] - mysum;                     // strictly-above count
    if (A < TOPK && A + mysum >= TOPK) {
        u32 acc = A;
        for (int bin = base + CH - 1; bin >= base; --bin) {
            u32 h = hist[bin];
            if (acc + h >= TOPK) { g_pbin[b] = (u32)bin; break; }
            acc += h;
        }
    }
}

// ---------------- kernel 3: compaction (4 elems/thread) ----------------
__global__ void k_compact(const float4* __restrict__ cls4) {
    u32 i = blockIdx.x * blockDim.x + threadIdx.x;   // group of 4 elements
    float4 p0 = cls4[2 * i];
    float4 p1 = cls4[2 * i + 1];
    u32 base = i << 2;
    u32 b = base >> NSHIFT;
    u32 p = g_pbin[b];
    float sc[4] = {p0.y, p0.w, p1.y, p1.w};
    #pragma unroll
    for (int k = 0; k < 4; k++) {
        u32 bits = __float_as_uint(sc[k]);
        u32 bin = min(bits >> BIN_SHIFT, (u32)(BINS - 1));
        u32 idx = (base + k) & (NELEM - 1);
        if (bin > p) {
            u32 pos = atomicAdd(&g_cnt_main[b], 1u);
            g_main[b * TOPK + pos] = ((u64)bits << 32) | (u32)(~idx);
        } else if (bin == p) {
            u32 pos = atomicAdd(&g_cnt_bnd[b], 1u);
            g_bnd[(u32)b * NELEM + pos] = ((u64)bits << 32) | (u32)(~idx);
        }
    }
}

// ---------------- kernel 4: sort keys, decode boxes -> global ----------------
__global__ void __launch_bounds__(1024, 1)
k_sort(const float4* __restrict__ bbox, const float4* __restrict__ anchors) {
    extern __shared__ __align__(16) unsigned char smem_raw[];
    u64* keys = (u64*)smem_raw;                  // 8192 * 8 = 65536

    int b = blockIdx.x;
    int tid = threadIdx.x;
    int lane = tid & 31;
    int wid = tid >> 5;

    u32 cnt_main = g_cnt_main[b];
    u32 m = g_cnt_bnd[b];
    u32 total = cnt_main + m;

    for (u32 i = tid; i < cnt_main; i += 1024) keys[i] = g_main[b * TOPK + i];

    if (total <= SORTN) {
        for (u32 i = tid; i < m; i += 1024) keys[cnt_main + i] = g_bnd[(u32)b * NELEM + i];
        for (u32 i = total + tid; i < SORTN; i += 1024) keys[i] = 0ull;
        __syncthreads();
    } else {
        // pathological fallback: iteratively select top-r boundary keys
        for (u32 i = cnt_main + tid; i < SORTN; i += 1024) keys[i] = 0ull;
        __syncthreads();
        __shared__ u64 rk[32];
        __shared__ u32 rp[32];
        int r = TOPK - (int)cnt_main;
        for (int round = 0; round < r; ++round) {
            u64 bk = 0; u32 bp = 0;
            for (u32 i = tid; i < m; i += 1024) {
                u64 v = g_bnd[(u32)b * NELEM + i];
                if (v > bk) { bk = v; bp = i; }
            }
            for (int off = 16; off; off >>= 1) {
                u64 ok = __shfl_down_sync(0xFFFFFFFFu, bk, off);
                u32 op = __shfl_down_sync(0xFFFFFFFFu, bp, off);
                if (ok > bk) { bk = ok; bp = op; }
            }
            if (lane == 0) { rk[wid] = bk; rp[wid] = bp; }
            __syncthreads();
            if (wid == 0) {
                bk = rk[lane]; bp = rp[lane];
                for (int off = 16; off; off >>= 1) {
                    u64 ok = __shfl_down_sync(0xFFFFFFFFu, bk, off);
                    u32 op = __shfl_down_sync(0xFFFFFFFFu, bp, off);
                    if (ok > bk) { bk = ok; bp = op; }
                }
                if (lane == 0) {
                    keys[cnt_main + round] = bk;
                    g_bnd[(u32)b * NELEM + bp] = 0ull;
                }
            }
            __syncthreads();
        }
    }

    // bitonic sort descending
    for (u32 k = 2; k <= SORTN; k <<= 1) {
        for (u32 j = k >> 1; j; j >>= 1) {
            for (u32 i = tid; i < SORTN; i += 1024) {
                u32 ix = i ^ j;
                if (ix > i) {
                    u64 a = keys[i], c = keys[ix];
                    bool dirDesc = ((i & k) == 0);
                    if ((a < c) == dirDesc) { keys[i] = c; keys[ix] = a; }
                }
            }
            __syncthreads();
        }
    }

    // decode boxes for top slots, write to global (+ zero pad)
    for (int s = tid; s < NPAD; s += 1024) {
        if (s < TOPK) {
            u64 key = keys[s];
            u32 idx = ~(u32)(key & 0xFFFFFFFFull);
            u32 gi = ((u32)b << NSHIFT) + idx;
            float4 a = anchors[gi];
            float4 d = bbox[gi];
            d.x *= 0.1f; d.y *= 0.1f; d.z *= 0.2f; d.w *= 0.2f;
            float h = a.z - a.x;
            float w = a.w - a.y;
            float cy = a.x + 0.5f * h;
            float cx = a.y + 0.5f * w;
            cy = cy + d.x * h;
            cx = cx + d.y * w;
            h = h * expf(d.z);
            w = w * expf(d.w);
            float4 box;
            box.x = fminf(fmaxf(cy - 0.5f * h, 0.0f), 1.0f);
            box.y = fminf(fmaxf(cx - 0.5f * w, 0.0f), 1.0f);
            box.z = fminf(fmaxf(cy + 0.5f * h, 0.0f), 1.0f);
            box.w = fminf(fmaxf(cx + 0.5f * w, 0.0f), 1.0f);
            g_sbox[b][s] = box;
            g_area[b][s] = (box.z - box.x) * (box.w - box.y);
        } else {
            g_sbox[b][s] = make_float4(0.0f, 0.0f, 0.0f, 0.0f);
            g_area[b][s] = 0.0f;
        }
    }
}

// ---------------- kernel 5: pairwise IoU suppression bitmask ----------------
// Division-free fast path: iou > 0.7  <=>  1.7*inter > 0.7*(areaA+areaC)
// Near-threshold pairs fall back to the exact reference-order division.
__global__ void __launch_bounds__(256) k_mask() {
    int cc  = blockIdx.x;            // column chunk 0..93
    int rc4 = blockIdx.y;            // row quad    0..23
    int b   = blockIdx.z;
    if (cc < (rc4 << 2)) return;     // entire block strictly lower-triangle

    __shared__ float4 cbox[64];
    __shared__ float  ca07[64];      // 0.7 * area
    __shared__ float  ca[64];        // exact area (fallback path)
    int t = threadIdx.x;
    int col0 = cc << 6;
    if (t < 64) {
        cbox[t] = g_sbox[b][col0 + t];
        float ar = g_area[b][col0 + t];
        ca[t] = ar;
        ca07[t] = 0.7f * ar;
    }
    __syncthreads();

    int rc = (rc4 << 2) + (t >> 6);
    if (rc > cc || rc >= NWORDS) return;
    int i = (rc << 6) + (t & 63);
    float4 a = g_sbox[b][i];
    float areaA = g_area[b][i];
    float a07 = 0.7f * areaA;

    u64 bits = 0, nearb = 0;
    if (cc != rc) {
        // off-diagonal: all 64 columns are strictly after row i
        #pragma unroll 16
        for (int j = 0; j < 64; j++) {
            float4 c = cbox[j];
            float y1 = fmaxf(a.x, c.x);
            float x1 = fmaxf(a.y, c.y);
            float y2 = fminf(a.z, c.z);
            float x2 = fminf(a.w, c.w);
            float inter = fmaxf(y2 - y1, 0.0f) * fmaxf(x2 - x1, 0.0f);
            float rhs = a07 + ca07[j];
            float d = fmaf(1.7f, inter, -rhs);
            float mg = fmaf(1e-4f, rhs, 1e-12f);
            if (d > 0.0f) bits |= (1ull << j);
            if (fabsf(d) < mg) nearb |= (1ull << j);
        }
    } else {
        #pragma unroll 16
        for (int j = 0; j < 64; j++) {
            if (col0 + j > i) {
                float4 c = cbox[j];
                float y1 = fmaxf(a.x, c.x);
                float x1 = fmaxf(a.y, c.y);
                float y2 = fminf(a.z, c.z);
                float x2 = fminf(a.w, c.w);
                float inter = fmaxf(y2 - y1, 0.0f) * fmaxf(x2 - x1, 0.0f);
                float rhs = a07 + ca07[j];
                float d = fmaf(1.7f, inter, -rhs);
                float mg = fmaf(1e-4f, rhs, 1e-12f);
                if (d > 0.0f) bits |= (1ull << j);
                if (fabsf(d) < mg) nearb |= (1ull << j);
            }
        }
    }

    // rare exact fixup (reference rounding order, IEEE div)
    while (nearb) {
        int j = __ffsll((long long)nearb) - 1;
        nearb &= nearb - 1;
        float4 c = cbox[j];
        float y1 = fmaxf(a.x, c.x);
        float x1 = fmaxf(a.y, c.y);
        float y2 = fminf(a.z, c.z);
        float x2 = fminf(a.w, c.w);
        float inter = fmaxf(y2 - y1, 0.0f) * fmaxf(x2 - x1, 0.0f);
        float denom = areaA + ca[j] - inter + 1e-9f;
        float iou = inter / denom;
        if (iou > NMS_THR) bits |= (1ull << j);
        else               bits &= ~(1ull << j);
    }

    g_mask[b][i][cc] = bits;
}

// ---------------- kernel 6: serial greedy pass over bitmasks ----------------
// Register-mirrored current word: critical chain is ffs -> broadcast LDG -> OR.
__global__ void __launch_bounds__(32) k_seq(float4* __restrict__ out) {
    int b = blockIdx.x;
    int lane = threadIdx.x;

    __shared__ u64 remv[NWORDS];
    for (int r = lane; r < NWORDS; r += 32) remv[r] = 0ull;

    const float4* sb = g_sbox[b];
    float4* ob = out + b * NOUT;
    int cnt = 0;

    // warm the L1 with the first rows
    {
        const char* pb = (const char*)&g_mask[b][0][0];
        asm volatile("prefetch.global.L1 [%0];" :: "l"(pb + (u32)lane * 128));
        asm volatile("prefetch.global.L1 [%0];" :: "l"(pb + (u32)(lane + 32) * 128));
        asm volatile("prefetch.global.L1 [%0];" :: "l"(pb + (u32)(lane + 64) * 128));
    }

    for (int w = 0; w < NWORDS && cnt < NOUT; w++) {
        __syncwarp();                                  // drain remv updates
        u64 live = (w == NWORDS - 1) ? ((1ull << 48) - 1ull) : ~0ull;
        u64 rw = (~remv[w]) & live;                    // one LDS per word

        while (cnt < NOUT && rw) {
            int bit = __ffsll((long long)rw) - 1;
            int i = (w << 6) + bit;
            const u64* row = &g_mask[b][i][0];

            if (lane == 0) ob[cnt] = sb[i];
            cnt++;

            // off critical path: fold row into remv for later words
            #pragma unroll
            for (int r = 0; r < 3; r++) {
                int j = lane + (r << 5);
                if (j < NWORDS && j > w) remv[j] |= row[j];
            }
            // prefetch the next ~16 rows into L1
            {
                const char* pb = (const char*)&g_mask[b][i + 1][0];
                asm volatile("prefetch.global.L1 [%0];" :: "l"(pb + (u32)lane * 128));
                asm volatile("prefetch.global.L1 [%0];" :: "l"(pb + (u32)(lane + 32) * 128));
                asm volatile("prefetch.global.L1 [%0];" :: "l"(pb + (u32)(lane + 64) * 128));
            }

            // critical path: broadcast load of current word, all lanes identical
            u64 mw = row[w];
            rw &= ~mw;
            rw &= ~(1ull << bit);
        }
    }

    for (int q = cnt + lane; q < NOUT; q += 32)
        ob[q] = make_float4(0.0f, 0.0f, 0.0f, 0.0f);
}

// ---------------- launch ----------------
extern "C" void kernel_launch(void* const* d_in, const int* in_sizes, int n_in,
                              void* d_out, int out_size) {
    const float4* cls4    = (const float4*)d_in[0];
    const float4* bbox    = (const float4*)d_in[1];
    const float4* anchors = (const float4*)d_in[2];
    float4* out = (float4*)d_out;

    (void)in_sizes; (void)n_in; (void)out_size;

    const int total = BATCH * NELEM;

    k_zero<<<(BATCH * BINS / 4) / 256, 256>>>();
    k_hist<<<(total / 4) / 256, 256>>>(cls4);
    k_select<<<BATCH, 1024>>>();
    k_compact<<<(total / 4) / 256, 256>>>(cls4);

    cudaFuncSetAttribute(k_sort, cudaFuncAttributeMaxDynamicSharedMemorySize, 65536);
    k_sort<<<BATCH, 1024, 65536>>>(bbox, anchors);

    dim3 mgrid(NWORDS, (NWORDS + 3) / 4, BATCH);
    k_mask<<<mgrid, 256>>>();

    k_seq<<<BATCH, 32>>>(out);
}